// round 9
// baseline (speedup 1.0000x reference)
#include <cuda_runtime.h>
#include <cstdint>

#define BB 2048
#define NN 512
#define UU 64
#define NT 256            // threads per CTA (8 warps)

#define TROWS 128         // rows cached in smem
#define TILE_F (TROWS * 64)   // 8192 floats = 32 KB
#define RP_STRIDE 68          // padded stride for r partials (16B aligned, low conflict)
#define SMEM_FLOATS (TILE_F + NN + NN + 16 * RP_STRIDE + 8)

// ---- block reductions (256 threads, 8 warps) ----
__device__ __forceinline__ float blockReduceSum(float v, float* scratch) {
    #pragma unroll
    for (int o = 16; o; o >>= 1) v += __shfl_xor_sync(0xffffffffu, v, o);
    int w = threadIdx.x >> 5, l = threadIdx.x & 31;
    if (l == 0) scratch[w] = v;
    __syncthreads();
    if (threadIdx.x < 8) {
        v = scratch[threadIdx.x];
        #pragma unroll
        for (int o = 4; o; o >>= 1) v += __shfl_xor_sync(0x000000ffu, v, o);
        if (threadIdx.x == 0) scratch[0] = v;
    }
    __syncthreads();
    return scratch[0];    // scratch only rewritten after a later barrier
}

__global__ __launch_bounds__(NT, 4) void ntm_kernel(
    const float* __restrict__ memory, const float* __restrict__ k,
    const float* __restrict__ beta_p, const float* __restrict__ g_p,
    const float* __restrict__ s,      const float* __restrict__ gamma_p,
    const float* __restrict__ w_pre,  const float* __restrict__ e,
    const float* __restrict__ a,
    float* __restrict__ out_w, float* __restrict__ out_r, float* __restrict__ out_m)
{
    extern __shared__ float dyn[];
    float* tile    = dyn;                    // 8192: rows 0..127
    float* arrA    = dyn + TILE_F;           // 512: sims -> final w
    float* arrB    = arrA + NN;              // 512: gated weights
    float* rpart   = arrB + NN;              // 16 * 68
    float* scratch = rpart + 16 * RP_STRIDE; // 8

    const int b   = blockIdx.x;
    const int tid = threadIdx.x;
    const int gid = tid >> 4;                // 0..15
    const int gl  = tid & 15;

    const float beta  = beta_p[0];
    const float gg    = g_p[0];
    const float gamma = gamma_p[0];

    const float* memb  = memory + ((long)b << 15);
    float*       outmb = out_m  + ((long)b << 15);

    // ---- k: each 16-lane group holds full k as 4 floats/lane; 1/||k|| via shuffles ----
    const float4 k4 = *(const float4*)(k + b * UU + gl * 4);
    float kq = k4.x * k4.x + k4.y * k4.y + k4.z * k4.z + k4.w * k4.w;
    #pragma unroll
    for (int o = 8; o; o >>= 1) kq += __shfl_xor_sync(0xffffffffu, kq, o);
    const float kninv = 1.f / fmaxf(sqrtf(kq), 1e-8f);

    // ---- phase 1: load + sims; rows<128 cached to smem ----
    // group gid owns rows gid + 16*i, i = 0..31
    #pragma unroll 4
    for (int i = 0; i < 8; ++i) {
        int row = gid + (i << 4);
        float4 m = *(const float4*)(memb + row * 64 + gl * 4);
        *(float4*)(tile + row * 64 + gl * 4) = m;
        float d = m.x * k4.x + m.y * k4.y + m.z * k4.z + m.w * k4.w;
        float q = m.x * m.x + m.y * m.y + m.z * m.z + m.w * m.w;
        #pragma unroll
        for (int o = 8; o; o >>= 1) {
            d += __shfl_xor_sync(0xffffffffu, d, o);
            q += __shfl_xor_sync(0xffffffffu, q, o);
        }
        if (gl == 0) arrA[row] = d / fmaxf(sqrtf(q), 1e-8f);   // ny deferred
    }
    #pragma unroll 4
    for (int i = 8; i < 32; ++i) {
        int row = gid + (i << 4);
        float4 m = *(const float4*)(memb + row * 64 + gl * 4);
        float d = m.x * k4.x + m.y * k4.y + m.z * k4.z + m.w * k4.w;
        float q = m.x * m.x + m.y * m.y + m.z * m.z + m.w * m.w;
        #pragma unroll
        for (int o = 8; o; o >>= 1) {
            d += __shfl_xor_sync(0xffffffffu, d, o);
            q += __shfl_xor_sync(0xffffffffu, q, o);
        }
        if (gl == 0) arrA[row] = d / fmaxf(sqrtf(q), 1e-8f);
    }
    __syncthreads();                        // publish arrA

    // ---- phase 2: softmax (no max-sub: |beta*sim| <= 5), gate, shift, sharpen ----
    const int n0 = tid, n1 = tid + 256;
    const float bn = beta * kninv;
    float e0 = expf(bn * arrA[n0]);
    float e1 = expf(bn * arrA[n1]);
    float esum = blockReduceSum(e0 + e1, scratch);
    float einv = 1.f / esum;
    arrB[n0] = gg * e0 * einv + (1.f - gg) * w_pre[b * NN + n0];
    arrB[n1] = gg * e1 * einv + (1.f - gg) * w_pre[b * NN + n1];
    __syncthreads();                        // publish arrB

    const float s0 = s[b * 3 + 0], s1 = s[b * 3 + 1], s2 = s[b * 3 + 2];
    float ws0 = s0 * arrB[(n0 + 511) & 511] + s1 * arrB[n0] + s2 * arrB[(n0 + 1) & 511];
    float ws1 = s0 * arrB[(n1 + 511) & 511] + s1 * arrB[n1] + s2 * arrB[(n1 + 1) & 511];
    float p0 = exp2f(gamma * log2f(ws0));   // ws > 0
    float p1 = exp2f(gamma * log2f(ws1));
    float psum = blockReduceSum(p0 + p1, scratch);
    float pinv = 1.f / psum;
    float w0 = p0 * pinv + 1e-16f;
    float w1 = p1 * pinv + 1e-16f;
    arrA[n0] = w0;
    arrA[n1] = w1;
    out_w[b * NN + n0] = w0;
    out_w[b * NN + n1] = w1;
    __syncthreads();                        // publish w

    // ---- phase 3: read (smem rows<128, L2 .cs for rest) + erase/add .cs store ----
    const float4 e4 = *(const float4*)(e + b * UU + gl * 4);
    const float4 a4 = *(const float4*)(a + b * UU + gl * 4);
    float4 racc = make_float4(0.f, 0.f, 0.f, 0.f);
    #pragma unroll 4
    for (int i = 0; i < 8; ++i) {
        int row = gid + (i << 4);
        float4 m = *(const float4*)(tile + row * 64 + gl * 4);
        float wn = arrA[row];
        racc.x += wn * m.x;  racc.y += wn * m.y;
        racc.z += wn * m.z;  racc.w += wn * m.w;
        float4 nm;
        nm.x = m.x * (1.f - wn * e4.x) + wn * a4.x;
        nm.y = m.y * (1.f - wn * e4.y) + wn * a4.y;
        nm.z = m.z * (1.f - wn * e4.z) + wn * a4.z;
        nm.w = m.w * (1.f - wn * e4.w) + wn * a4.w;
        __stcs((float4*)(outmb + row * 64 + gl * 4), nm);
    }
    #pragma unroll 4
    for (int i = 8; i < 32; ++i) {
        int row = gid + (i << 4);
        float4 m = __ldcs((const float4*)(memb + row * 64 + gl * 4));  // L2 hit, last use
        float wn = arrA[row];
        racc.x += wn * m.x;  racc.y += wn * m.y;
        racc.z += wn * m.z;  racc.w += wn * m.w;
        float4 nm;
        nm.x = m.x * (1.f - wn * e4.x) + wn * a4.x;
        nm.y = m.y * (1.f - wn * e4.y) + wn * a4.y;
        nm.z = m.z * (1.f - wn * e4.z) + wn * a4.z;
        nm.w = m.w * (1.f - wn * e4.w) + wn * a4.w;
        __stcs((float4*)(outmb + row * 64 + gl * 4), nm);
    }

    // ---- r epilogue: 16 group-partials -> 1 ----
    *(float4*)&rpart[gid * RP_STRIDE + gl * 4] = racc;
    __syncthreads();
    if (tid < UU) {
        float rs = 0.f;
        #pragma unroll
        for (int gx = 0; gx < 16; ++gx) rs += rpart[gx * RP_STRIDE + tid];
        out_r[b * UU + tid] = rs;
    }
}

extern "C" void kernel_launch(void* const* d_in, const int* in_sizes, int n_in,
                              void* d_out, int out_size) {
    const float* memory = (const float*)d_in[0];
    const float* k      = (const float*)d_in[1];
    const float* beta   = (const float*)d_in[2];
    const float* g      = (const float*)d_in[3];
    const float* s      = (const float*)d_in[4];
    const float* gamma  = (const float*)d_in[5];
    const float* w_pre  = (const float*)d_in[6];
    const float* e      = (const float*)d_in[7];
    const float* a      = (const float*)d_in[8];

    float* out   = (float*)d_out;
    float* out_w = out;                               // (B, N)
    float* out_r = out_w + (long)BB * NN;             // (B, U)
    float* out_m = out_r + (long)BB * UU;             // (B, N, U)

    const int smem_bytes = SMEM_FLOATS * sizeof(float);
    cudaFuncSetAttribute(ntm_kernel,
                         cudaFuncAttributeMaxDynamicSharedMemorySize,
                         smem_bytes);

    ntm_kernel<<<BB, NT, smem_bytes>>>(memory, k, beta, g, s, gamma, w_pre, e, a,
                                       out_w, out_r, out_m);
}

// round 13
// speedup vs baseline: 1.2615x; 1.2615x over previous
#include <cuda_runtime.h>
#include <cstdint>

#define BB 2048
#define NN 512
#define UU 64
#define NT 256              // threads per CTA (8 warps)

#define CROWS 64            // rows per chunk
#define CHUNK_F (CROWS * 64)    // 4096 floats = 16 KB
#define NCHUNK 8
#define RP_STRIDE 68
// buf0 + buf1 + arrA + arrB + ksm + rpart + scratch
#define SMEM_FLOATS (2 * CHUNK_F + NN + NN + UU + 16 * RP_STRIDE + 8)

__device__ __forceinline__ void cp_async16(float* smem_dst, const float* gsrc) {
    uint32_t sa = (uint32_t)__cvta_generic_to_shared(smem_dst);
    asm volatile("cp.async.cg.shared.global [%0], [%1], 16;" :: "r"(sa), "l"(gsrc));
}

// ---- block reduction (256 threads, 8 warps) ----
__device__ __forceinline__ float blockReduceSum(float v, float* scratch) {
    #pragma unroll
    for (int o = 16; o; o >>= 1) v += __shfl_xor_sync(0xffffffffu, v, o);
    int w = threadIdx.x >> 5, l = threadIdx.x & 31;
    if (l == 0) scratch[w] = v;
    __syncthreads();
    if (threadIdx.x < 8) {
        v = scratch[threadIdx.x];
        #pragma unroll
        for (int o = 4; o; o >>= 1) v += __shfl_xor_sync(0x000000ffu, v, o);
        if (threadIdx.x == 0) scratch[0] = v;
    }
    __syncthreads();
    return scratch[0];
}

__global__ __launch_bounds__(NT, 5) void ntm_kernel(
    const float* __restrict__ memory, const float* __restrict__ k,
    const float* __restrict__ beta_p, const float* __restrict__ g_p,
    const float* __restrict__ s,      const float* __restrict__ gamma_p,
    const float* __restrict__ w_pre,  const float* __restrict__ e,
    const float* __restrict__ a,
    float* __restrict__ out_w, float* __restrict__ out_r, float* __restrict__ out_m)
{
    extern __shared__ float dyn[];
    float* buf     = dyn;                      // 2 * 4096
    float* arrA    = dyn + 2 * CHUNK_F;        // 512: sims -> final w
    float* arrB    = arrA + NN;                // 512
    float* ksm     = arrB + NN;                // 64
    float* rpart   = ksm + UU;                 // 16*68
    float* scratch = rpart + 16 * RP_STRIDE;   // 8

    const int b   = blockIdx.x;
    const int tid = threadIdx.x;
    const int rr  = tid >> 2;                  // 0..63: row within chunk
    const int qq  = tid & 3;                   // quarter of row
    const int gid = tid >> 4;                  // 0..15 (phase 3)
    const int gl  = tid & 15;

    const float beta  = beta_p[0];
    const float gg    = g_p[0];
    const float gamma = gamma_p[0];

    const float* memb  = memory + ((long)b << 15);
    float*       outmb = out_m  + ((long)b << 15);

    // ---- stage k; prologue: issue chunks 0 and 1 ----
    // chunk c occupies floats [c*CHUNK_F, (c+1)*CHUNK_F) of memb; f is a float4 idx
    if (tid < UU) ksm[tid] = k[b * UU + tid];
    #pragma unroll
    for (int t = 0; t < 4; ++t) {
        int f = tid + (t << 8);
        cp_async16(buf + f * 4, memb + f * 4);
    }
    asm volatile("cp.async.commit_group;");
    #pragma unroll
    for (int t = 0; t < 4; ++t) {
        int f = tid + (t << 8);
        cp_async16(buf + CHUNK_F + f * 4, memb + CHUNK_F + f * 4);
    }
    asm volatile("cp.async.commit_group;");

    // ---- phase 1: chunked sims, double-buffered ----
    for (int c = 0; c < NCHUNK; ++c) {
        asm volatile("cp.async.wait_group 1;");
        __syncthreads();                       // chunk c visible to all (+ksm on c==0)
        float* cb = buf + (c & 1) * CHUNK_F;
        float d = 0.f, q = 0.f;
        #pragma unroll
        for (int j = 0; j < 4; ++j) {
            int v = (((rr + j) & 3) << 2) + qq;        // distinct float4 per lane-phase
            float4 m = *(const float4*)(cb + rr * 64 + v * 4);
            float4 kv = *(const float4*)(ksm + v * 4);
            d += m.x * kv.x + m.y * kv.y + m.z * kv.z + m.w * kv.w;
            q += m.x * m.x + m.y * m.y + m.z * m.z + m.w * m.w;
        }
        // reduce over the 4 quarters of the row (lanes xor1, xor2)
        d += __shfl_xor_sync(0xffffffffu, d, 1);
        q += __shfl_xor_sync(0xffffffffu, q, 1);
        d += __shfl_xor_sync(0xffffffffu, d, 2);
        q += __shfl_xor_sync(0xffffffffu, q, 2);
        if (qq == 0) arrA[c * CROWS + rr] = d / fmaxf(sqrtf(q), 1e-8f);  // ny deferred
        __syncthreads();                       // all reads of this buffer done
        if (c + 2 < NCHUNK) {
            #pragma unroll
            for (int t = 0; t < 4; ++t) {
                int f = tid + (t << 8);
                cp_async16(cb + f * 4, memb + (c + 2) * CHUNK_F + f * 4);
            }
        }
        asm volatile("cp.async.commit_group;");
    }

    // ---- phase 2: softmax (no max-sub: |beta*sim| <= 5), gate, shift, sharpen ----
    float kq;
    {
        const float4 ka = *(const float4*)(ksm + gl * 4);
        kq = ka.x * ka.x + ka.y * ka.y + ka.z * ka.z + ka.w * ka.w;
        #pragma unroll
        for (int o = 8; o; o >>= 1) kq += __shfl_xor_sync(0xffffffffu, kq, o);
    }
    const float bn = beta / fmaxf(sqrtf(kq), 1e-8f);
    const int n0 = tid, n1 = tid + 256;
    float e0 = expf(bn * arrA[n0]);
    float e1 = expf(bn * arrA[n1]);
    float esum = blockReduceSum(e0 + e1, scratch);
    float einv = 1.f / esum;
    arrB[n0] = gg * e0 * einv + (1.f - gg) * w_pre[b * NN + n0];
    arrB[n1] = gg * e1 * einv + (1.f - gg) * w_pre[b * NN + n1];
    __syncthreads();

    const float s0 = s[b * 3 + 0], s1 = s[b * 3 + 1], s2 = s[b * 3 + 2];
    float ws0 = s0 * arrB[(n0 + 511) & 511] + s1 * arrB[n0] + s2 * arrB[(n0 + 1) & 511];
    float ws1 = s0 * arrB[(n1 + 511) & 511] + s1 * arrB[n1] + s2 * arrB[(n1 + 1) & 511];
    float p0 = exp2f(gamma * log2f(ws0));   // ws > 0
    float p1 = exp2f(gamma * log2f(ws1));
    float psum = blockReduceSum(p0 + p1, scratch);
    float pinv = 1.f / psum;
    float w0 = p0 * pinv + 1e-16f;
    float w1 = p1 * pinv + 1e-16f;
    arrA[n0] = w0;
    arrA[n1] = w1;
    out_w[b * NN + n0] = w0;
    out_w[b * NN + n1] = w1;
    __syncthreads();

    // ---- phase 3: L2 re-read (__ldcs) + fused r + erase/add (__stcs) ----
    const float4 e4 = *(const float4*)(e + b * UU + gl * 4);
    const float4 a4 = *(const float4*)(a + b * UU + gl * 4);
    float4 racc = make_float4(0.f, 0.f, 0.f, 0.f);
    #pragma unroll 8
    for (int i = 0; i < 32; ++i) {
        int row = gid + (i << 4);
        float4 m = __ldcs((const float4*)(memb + row * 64 + gl * 4));
        float wn = arrA[row];
        racc.x += wn * m.x;  racc.y += wn * m.y;
        racc.z += wn * m.z;  racc.w += wn * m.w;
        float4 nm;
        nm.x = m.x * (1.f - wn * e4.x) + wn * a4.x;
        nm.y = m.y * (1.f - wn * e4.y) + wn * a4.y;
        nm.z = m.z * (1.f - wn * e4.z) + wn * a4.z;
        nm.w = m.w * (1.f - wn * e4.w) + wn * a4.w;
        __stcs((float4*)(outmb + row * 64 + gl * 4), nm);
    }

    // ---- r epilogue ----
    *(float4*)&rpart[gid * RP_STRIDE + gl * 4] = racc;
    __syncthreads();
    if (tid < UU) {
        float rs = 0.f;
        #pragma unroll
        for (int gx = 0; gx < 16; ++gx) rs += rpart[gx * RP_STRIDE + tid];
        out_r[b * UU + tid] = rs;
    }
}

extern "C" void kernel_launch(void* const* d_in, const int* in_sizes, int n_in,
                              void* d_out, int out_size) {
    const float* memory = (const float*)d_in[0];
    const float* k      = (const float*)d_in[1];
    const float* beta   = (const float*)d_in[2];
    const float* g      = (const float*)d_in[3];
    const float* s      = (const float*)d_in[4];
    const float* gamma  = (const float*)d_in[5];
    const float* w_pre  = (const float*)d_in[6];
    const float* e      = (const float*)d_in[7];
    const float* a      = (const float*)d_in[8];

    float* out   = (float*)d_out;
    float* out_w = out;                               // (B, N)
    float* out_r = out_w + (long)BB * NN;             // (B, U)
    float* out_m = out_r + (long)BB * UU;             // (B, N, U)

    const int smem_bytes = SMEM_FLOATS * sizeof(float);
    cudaFuncSetAttribute(ntm_kernel,
                         cudaFuncAttributeMaxDynamicSharedMemorySize,
                         smem_bytes);

    ntm_kernel<<<BB, NT, smem_bytes>>>(memory, k, beta, g, s, gamma, w_pre, e, a,
                                       out_w, out_r, out_m);
}

// round 17
// speedup vs baseline: 1.3435x; 1.0650x over previous
#include <cuda_runtime.h>
#include <cstdint>

#define BB 2048
#define NN 512
#define UU 64
#define NT 256              // threads per CTA (8 warps)

#define CROWS 64            // rows per chunk
#define CHUNK_F (CROWS * 64)    // 4096 floats = 16 KB
#define NCHUNK 8
#define RP_STRIDE 68
// buf0+buf1 (pipeline, then chunk6/7 retention, then r-partials) + arrA + arrB + ksm + scratch
#define SMEM_FLOATS (2 * CHUNK_F + NN + NN + UU + 8)

__device__ __forceinline__ void cp_async16(float* smem_dst, const float* gsrc) {
    uint32_t sa = (uint32_t)__cvta_generic_to_shared(smem_dst);
    asm volatile("cp.async.cg.shared.global [%0], [%1], 16;" :: "r"(sa), "l"(gsrc));
}

// ---- block reduction (256 threads, 8 warps) ----
__device__ __forceinline__ float blockReduceSum(float v, float* scratch) {
    #pragma unroll
    for (int o = 16; o; o >>= 1) v += __shfl_xor_sync(0xffffffffu, v, o);
    int w = threadIdx.x >> 5, l = threadIdx.x & 31;
    if (l == 0) scratch[w] = v;
    __syncthreads();
    if (threadIdx.x < 8) {
        v = scratch[threadIdx.x];
        #pragma unroll
        for (int o = 4; o; o >>= 1) v += __shfl_xor_sync(0x000000ffu, v, o);
        if (threadIdx.x == 0) scratch[0] = v;
    }
    __syncthreads();
    return scratch[0];
}

__global__ __launch_bounds__(NT, 5) void ntm_kernel(
    const float* __restrict__ memory, const float* __restrict__ k,
    const float* __restrict__ beta_p, const float* __restrict__ g_p,
    const float* __restrict__ s,      const float* __restrict__ gamma_p,
    const float* __restrict__ w_pre,  const float* __restrict__ e,
    const float* __restrict__ a,
    float* __restrict__ out_w, float* __restrict__ out_r, float* __restrict__ out_m)
{
    extern __shared__ float dyn[];
    float* buf     = dyn;                      // 2 * 4096 (pipeline / retention / rpart)
    float* arrA    = dyn + 2 * CHUNK_F;        // 512: sims -> final w
    float* arrB    = arrA + NN;                // 512
    float* ksm     = arrB + NN;                // 64
    float* scratch = ksm + UU;                 // 8

    const int b   = blockIdx.x;
    const int tid = threadIdx.x;
    const int rr  = tid >> 2;                  // 0..63: row within chunk
    const int qq  = tid & 3;                   // quarter of row
    const int gid = tid >> 4;                  // 0..15 (phase 3)
    const int gl  = tid & 15;

    const float beta  = beta_p[0];
    const float gg    = g_p[0];
    const float gamma = gamma_p[0];

    const float* memb  = memory + ((long)b << 15);
    float*       outmb = out_m  + ((long)b << 15);

    // ---- stage k; prologue: issue chunks 0 and 1 ----
    if (tid < UU) ksm[tid] = k[b * UU + tid];
    #pragma unroll
    for (int t = 0; t < 4; ++t) {
        int f = tid + (t << 8);
        cp_async16(buf + f * 4, memb + f * 4);
    }
    asm volatile("cp.async.commit_group;");
    #pragma unroll
    for (int t = 0; t < 4; ++t) {
        int f = tid + (t << 8);
        cp_async16(buf + CHUNK_F + f * 4, memb + CHUNK_F + f * 4);
    }
    asm volatile("cp.async.commit_group;");

    // ---- phase 1: chunked sims, double-buffered; chunks 6,7 stay resident ----
    for (int c = 0; c < NCHUNK; ++c) {
        asm volatile("cp.async.wait_group 1;");
        __syncthreads();                       // chunk c visible (+ksm on c==0)
        float* cb = buf + (c & 1) * CHUNK_F;
        float d = 0.f, q = 0.f;
        #pragma unroll
        for (int j = 0; j < 4; ++j) {
            int v = (((rr + j) & 3) << 2) + qq;        // distinct float4 per lane-phase
            float4 m = *(const float4*)(cb + rr * 64 + v * 4);
            float4 kv = *(const float4*)(ksm + v * 4);
            d += m.x * kv.x + m.y * kv.y + m.z * kv.z + m.w * kv.w;
            q += m.x * m.x + m.y * m.y + m.z * m.z + m.w * m.w;
        }
        d += __shfl_xor_sync(0xffffffffu, d, 1);
        q += __shfl_xor_sync(0xffffffffu, q, 1);
        d += __shfl_xor_sync(0xffffffffu, d, 2);
        q += __shfl_xor_sync(0xffffffffu, q, 2);
        if (qq == 0) arrA[c * CROWS + rr] = d / fmaxf(sqrtf(q), 1e-8f);  // ny deferred
        __syncthreads();                       // all reads of this buffer done
        if (c + 2 < NCHUNK) {
            #pragma unroll
            for (int t = 0; t < 4; ++t) {
                int f = tid + (t << 8);
                cp_async16(cb + f * 4, memb + (c + 2) * CHUNK_F + f * 4);
            }
        }
        asm volatile("cp.async.commit_group;");
    }
    // buf slot 0 now holds chunk 6 (rows 384..447), slot 1 holds chunk 7 (rows 448..511)

    // ---- phase 2: softmax (no max-sub: |beta*sim| <= 5), gate, shift, sharpen ----
    float kq;
    {
        const float4 ka = *(const float4*)(ksm + gl * 4);
        kq = ka.x * ka.x + ka.y * ka.y + ka.z * ka.z + ka.w * ka.w;
        #pragma unroll
        for (int o = 8; o; o >>= 1) kq += __shfl_xor_sync(0xffffffffu, kq, o);
    }
    const float bn = beta / fmaxf(sqrtf(kq), 1e-8f);
    const int n0 = tid, n1 = tid + 256;
    float e0 = expf(bn * arrA[n0]);
    float e1 = expf(bn * arrA[n1]);
    float esum = blockReduceSum(e0 + e1, scratch);
    float einv = 1.f / esum;
    arrB[n0] = gg * e0 * einv + (1.f - gg) * w_pre[b * NN + n0];
    arrB[n1] = gg * e1 * einv + (1.f - gg) * w_pre[b * NN + n1];
    __syncthreads();

    const float s0 = s[b * 3 + 0], s1 = s[b * 3 + 1], s2 = s[b * 3 + 2];
    float ws0 = s0 * arrB[(n0 + 511) & 511] + s1 * arrB[n0] + s2 * arrB[(n0 + 1) & 511];
    float ws1 = s0 * arrB[(n1 + 511) & 511] + s1 * arrB[n1] + s2 * arrB[(n1 + 1) & 511];
    float p0 = exp2f(gamma * log2f(ws0));   // ws > 0
    float p1 = exp2f(gamma * log2f(ws1));
    float psum = blockReduceSum(p0 + p1, scratch);
    float pinv = 1.f / psum;
    float w0 = p0 * pinv + 1e-16f;
    float w1 = p1 * pinv + 1e-16f;
    arrA[n0] = w0;
    arrA[n1] = w1;
    out_w[b * NN + n0] = w0;
    out_w[b * NN + n1] = w1;
    __syncthreads();

    // ---- phase 3: rows 0..383 from L2 (__ldcs), rows 384..511 from retained smem ----
    const float4 e4 = *(const float4*)(e + b * UU + gl * 4);
    const float4 a4 = *(const float4*)(a + b * UU + gl * 4);
    float4 racc = make_float4(0.f, 0.f, 0.f, 0.f);
    #pragma unroll 8
    for (int i = 0; i < 24; ++i) {
        int row = gid + (i << 4);
        float4 m = __ldcs((const float4*)(memb + row * 64 + gl * 4));
        float wn = arrA[row];
        racc.x += wn * m.x;  racc.y += wn * m.y;
        racc.z += wn * m.z;  racc.w += wn * m.w;
        float4 nm;
        nm.x = m.x * (1.f - wn * e4.x) + wn * a4.x;
        nm.y = m.y * (1.f - wn * e4.y) + wn * a4.y;
        nm.z = m.z * (1.f - wn * e4.z) + wn * a4.z;
        nm.w = m.w * (1.f - wn * e4.w) + wn * a4.w;
        __stcs((float4*)(outmb + row * 64 + gl * 4), nm);
    }
    #pragma unroll
    for (int i = 24; i < 32; ++i) {
        int row = gid + (i << 4);                      // 384..511
        int ch  = row >> 6;                            // 6 or 7
        const float* cb = buf + (ch & 1) * CHUNK_F;
        float4 m = *(const float4*)(cb + (row & 63) * 64 + gl * 4);
        float wn = arrA[row];
        racc.x += wn * m.x;  racc.y += wn * m.y;
        racc.z += wn * m.z;  racc.w += wn * m.w;
        float4 nm;
        nm.x = m.x * (1.f - wn * e4.x) + wn * a4.x;
        nm.y = m.y * (1.f - wn * e4.y) + wn * a4.y;
        nm.z = m.z * (1.f - wn * e4.z) + wn * a4.z;
        nm.w = m.w * (1.f - wn * e4.w) + wn * a4.w;
        __stcs((float4*)(outmb + row * 64 + gl * 4), nm);
    }

    // ---- r epilogue: partials into buf (free now) ----
    __syncthreads();                          // all smem reads (buf, arrA) complete
    *(float4*)&buf[gid * RP_STRIDE + gl * 4] = racc;
    __syncthreads();
    if (tid < UU) {
        float rs = 0.f;
        #pragma unroll
        for (int gx = 0; gx < 16; ++gx) rs += buf[gx * RP_STRIDE + tid];
        out_r[b * UU + tid] = rs;
    }
}

extern "C" void kernel_launch(void* const* d_in, const int* in_sizes, int n_in,
                              void* d_out, int out_size) {
    const float* memory = (const float*)d_in[0];
    const float* k      = (const float*)d_in[1];
    const float* beta   = (const float*)d_in[2];
    const float* g      = (const float*)d_in[3];
    const float* s      = (const float*)d_in[4];
    const float* gamma  = (const float*)d_in[5];
    const float* w_pre  = (const float*)d_in[6];
    const float* e      = (const float*)d_in[7];
    const float* a      = (const float*)d_in[8];

    float* out   = (float*)d_out;
    float* out_w = out;                               // (B, N)
    float* out_r = out_w + (long)BB * NN;             // (B, U)
    float* out_m = out_r + (long)BB * UU;             // (B, N, U)

    const int smem_bytes = SMEM_FLOATS * sizeof(float);
    cudaFuncSetAttribute(ntm_kernel,
                         cudaFuncAttributeMaxDynamicSharedMemorySize,
                         smem_bytes);

    ntm_kernel<<<BB, NT, smem_bytes>>>(memory, k, beta, g, s, gamma, w_pre, e, a,
                                       out_w, out_r, out_m);
}